// round 16
// baseline (speedup 1.0000x reference)
#include <cuda_runtime.h>
#include <cstdint>
#include <cstddef>

#define T_STEPS 2048
#define H_DIM   512
#define B_DIM   32
#define D_IN    128
#define ALPHA   0.1f

// progress flags: done_flags[b*16 + tchunk] counts finished col-tiles (of 4)
__device__ int done_flags[B_DIM * 16];

__global__ void flags_zero() { done_flags[threadIdx.x] = 0; }

// ---------------------------------------------------------------------------
__device__ __forceinline__ int ld_acquire(const int* p) {
    int v;
    asm volatile("ld.acquire.gpu.global.b32 %0, [%1];" : "=r"(v) : "l"(p));
    return v;
}

__device__ __forceinline__ void wait_chunk(const int* p) {
    while (ld_acquire(p) < 4) __nanosleep(60);
}

__device__ __forceinline__ unsigned long long f2add(unsigned long long a,
                                                    unsigned long long b) {
    unsigned long long r;
    asm("add.rn.f32x2 %0, %1, %2;" : "=l"(r) : "l"(a), "l"(b));
    return r;
}

// mbarrier helpers (Hopper+ ISA, valid on sm_103a)
__device__ __forceinline__ void mbar_init(uint32_t addr, uint32_t count) {
    asm volatile("mbarrier.init.shared.b64 [%0], %1;" :: "r"(addr), "r"(count)
                 : "memory");
}
__device__ __forceinline__ void mbar_arrive(uint32_t addr) {
    asm volatile("mbarrier.arrive.shared.b64 _, [%0];" :: "r"(addr) : "memory");
}
__device__ __forceinline__ void mbar_wait(uint32_t addr, uint32_t parity) {
    uint32_t done;
    asm volatile(
        "{\n\t.reg .pred p;\n\t"
        "mbarrier.try_wait.parity.acquire.cta.shared::cta.b64 p, [%1], %2;\n\t"
        "selp.b32 %0, 1, 0, p;\n\t}"
        : "=r"(done) : "r"(addr), "r"(parity) : "memory");
    if (!done) {
        asm volatile(
            "{\n\t.reg .pred P1;\n\t"
            "WL_%=:\n\t"
            "mbarrier.try_wait.parity.acquire.cta.shared::cta.b64 P1, [%0], %1, 0x989680;\n\t"
            "@P1 bra.uni WD_%=;\n\t"
            "bra.uni WL_%=;\n\t"
            "WD_%=:\n\t}"
            :: "r"(addr), "r"(parity) : "memory");
    }
}

// ---------------------------------------------------------------------------
// Fused kernel.
//   bid 0..31    : scanner for batch b=bid (threads 0..127; 128..255 exit)
//   bid 32..2079 : one 128x128 GEMM tile of x_proj = x @ I^T, t-chunk-major
// ---------------------------------------------------------------------------
__global__ __launch_bounds__(256) void fused(const float* __restrict__ x,
                                             const float* __restrict__ m,
                                             const float* __restrict__ n,
                                             const float* __restrict__ I,
                                             float* __restrict__ out) {
    __shared__ __align__(16) float pool[2048];   // 8 KB: gemm As/Bs | scan state
    const int bid = blockIdx.x;

    if (bid >= B_DIM) {
        // ================= GEMM role =================
        const int g   = bid - B_DIM;
        const int tc  = g >> 7;          // t-chunk 0..15
        const int rem = g & 127;
        const int bb  = rem >> 2;        // batch 0..31
        const int bn4 = rem & 3;         // col tile 0..3
        const int row0 = bb * T_STEPS + tc * 128;
        const int col0 = bn4 * 128;

        float (*As)[128] = (float(*)[128])(pool);          // [8][128]
        float (*Bs)[128] = (float(*)[128])(pool + 1024);   // [8][128]

        const int tid = threadIdx.x;
        const int lr = tid >> 1;
        const int lc = (tid & 1) * 4;
        const float* Ap = x + (size_t)(row0 + lr) * D_IN + lc;
        const float* Bp = I + (size_t)(col0 + lr) * D_IN + lc;

        const int tx = (tid & 15) * 8;
        const int ty = (tid >> 4) * 8;

        float acc[8][8] = {};

        for (int k0 = 0; k0 < D_IN; k0 += 8) {
            const float4 av = *(const float4*)(Ap + k0);
            const float4 bv = *(const float4*)(Bp + k0);
            __syncthreads();
            As[lc + 0][lr] = av.x; As[lc + 1][lr] = av.y;
            As[lc + 2][lr] = av.z; As[lc + 3][lr] = av.w;
            Bs[lc + 0][lr] = bv.x; Bs[lc + 1][lr] = bv.y;
            Bs[lc + 2][lr] = bv.z; Bs[lc + 3][lr] = bv.w;
            __syncthreads();

            #pragma unroll
            for (int k = 0; k < 8; k++) {
                float a[8], bb2[8];
                *(float4*)&a[0]   = *(const float4*)&As[k][ty];
                *(float4*)&a[4]   = *(const float4*)&As[k][ty + 4];
                *(float4*)&bb2[0] = *(const float4*)&Bs[k][tx];
                *(float4*)&bb2[4] = *(const float4*)&Bs[k][tx + 4];
                #pragma unroll
                for (int i = 0; i < 8; i++)
                    #pragma unroll
                    for (int j = 0; j < 8; j++)
                        acc[i][j] = fmaf(a[i], bb2[j], acc[i][j]);
            }
        }

        #pragma unroll
        for (int i = 0; i < 8; i++) {
            float* Cp = out + (size_t)(row0 + ty + i) * H_DIM + col0 + tx;
            *(float4*)(Cp)     = make_float4(acc[i][0], acc[i][1], acc[i][2], acc[i][3]);
            *(float4*)(Cp + 4) = make_float4(acc[i][4], acc[i][5], acc[i][6], acc[i][7]);
        }

        __syncthreads();
        if (tid == 0) {
            __threadfence();             // release stores
            atomicAdd(&done_flags[bb * 16 + tc], 1);
        }
        return;
    }

    // ================= scanner role =================
    if (threadIdx.x >= 128) return;

    const int b    = bid;
    const int tid  = threadIdx.x;
    const int lane = tid & 31;
    const int wid  = tid >> 5;
    const float OMA = 1.0f - ALPHA;

    float2 (*part)[16] = (float2(*)[16])(pool);                   // [2][16]
    const uint32_t mbar =
        (uint32_t)__cvta_generic_to_shared(pool + 64);            // 8B, aligned

    if (tid == 0) mbar_init(mbar, 16);     // 16 arrivals per phase (lanes 0-3 x 4 warps)
    asm volatile("bar.sync 1, 128;" ::: "memory");

    // per-h constants (h = tid*4 + k)
    float n0[4], n1[4], am0[4], am1[4];
    {
        const float4 na = *(const float4*)(n + 8 * tid);
        const float4 nb = *(const float4*)(n + 8 * tid + 4);
        n0[0] = na.x; n1[0] = na.y; n0[1] = na.z; n1[1] = na.w;
        n0[2] = nb.x; n1[2] = nb.y; n0[3] = nb.z; n1[3] = nb.w;
        const float4 ma = *(const float4*)(m + 8 * tid);
        const float4 mb = *(const float4*)(m + 8 * tid + 4);
        am0[0] = ALPHA * ma.x; am1[0] = ALPHA * ma.y;
        am0[1] = ALPHA * ma.z; am1[1] = ALPHA * ma.w;
        am0[2] = ALPHA * mb.x; am1[2] = ALPHA * mb.y;
        am0[3] = ALPHA * mb.z; am1[3] = ALPHA * mb.w;
    }

    float* base = out + (size_t)b * T_STEPS * H_DIM + tid * 4;

    float hs[4] = {0.0f, 0.0f, 0.0f, 0.0f};

    // gate: only chunk 0 needed before the initial prefetch (rows 0..3)
    wait_chunk(&done_flags[b * 16 + 0]);

    float4 xp[4];
    #pragma unroll
    for (int d = 0; d < 4; d++) xp[d] = *(const float4*)(base + (size_t)d * H_DIM);

    #pragma unroll 1
    for (int t = 0; t < T_STEPS; t += 4) {
        // gate chunk c+1 just before the prefetch window crosses into it
        // (iters t=124.. prefetch rows 128..; gate fires at t&127==120)
        if ((t & 127) == 120) {
            int c1 = (t >> 7) + 1;
            if (c1 > 15) c1 = 15;
            wait_chunk(&done_flags[b * 16 + c1]);
        }

        #pragma unroll
        for (int u = 0; u < 4; u++) {
            const int tt = t + u;
            const float4 x4 = xp[u];

            float th[4];
            #pragma unroll
            for (int k = 0; k < 4; k++)
                asm("tanh.approx.f32 %0, %1;" : "=f"(th[k]) : "f"(hs[k]));

            float p0 = fmaf(th[1], n0[1], th[0] * n0[0]) +
                       fmaf(th[3], n0[3], th[2] * n0[2]);
            float p1 = fmaf(th[1], n1[1], th[0] * n1[0]) +
                       fmaf(th[3], n1[3], th[2] * n1[2]);

            float v[4];
            v[0] = fmaf(ALPHA, x4.x, OMA * hs[0]);
            v[1] = fmaf(ALPHA, x4.y, OMA * hs[1]);
            v[2] = fmaf(ALPHA, x4.z, OMA * hs[2]);
            v[3] = fmaf(ALPHA, x4.w, OMA * hs[3]);

            // 3-level butterfly: lanes 0-3 hold coset partials
            #pragma unroll
            for (int o = 16; o >= 4; o >>= 1) {
                p0 += __shfl_xor_sync(0xffffffffu, p0, o);
                p1 += __shfl_xor_sync(0xffffffffu, p1, o);
            }

            const int par = tt & 1;
            // post + arrive: each posting lane arrives, so its own store is
            // release-ordered w.r.t. acquire waiters (count = 16)
            if (lane < 4) {
                part[par][wid * 4 + lane] = make_float2(p0, p1);
                mbar_arrive(mbar);
            }

            // off-chain prefetch while the mbarrier fills
            if (tt + 4 < T_STEPS)
                xp[u] = *(const float4*)(base + (size_t)(tt + 4) * H_DIM);

            mbar_wait(mbar, (uint32_t)par);

            // gather 16 float2 partials with packed f32x2 adds
            const ulonglong2* pp = (const ulonglong2*)&part[par][0];
            unsigned long long r[8];
            #pragma unroll
            for (int w = 0; w < 8; w++) {
                const ulonglong2 q = pp[w];
                r[w] = f2add(q.x, q.y);
            }
            r[0] = f2add(r[0], r[1]); r[2] = f2add(r[2], r[3]);
            r[4] = f2add(r[4], r[5]); r[6] = f2add(r[6], r[7]);
            r[0] = f2add(r[0], r[2]); r[4] = f2add(r[4], r[6]);
            r[0] = f2add(r[0], r[4]);

            float s0, s1;
            asm("mov.b64 {%0, %1}, %2;" : "=f"(s0), "=f"(s1) : "l"(r[0]));

            float4 o4;
            hs[0] = fmaf(am0[0], s0, fmaf(am1[0], s1, v[0])); o4.x = hs[0];
            hs[1] = fmaf(am0[1], s0, fmaf(am1[1], s1, v[1])); o4.y = hs[1];
            hs[2] = fmaf(am0[2], s0, fmaf(am1[2], s1, v[2])); o4.z = hs[2];
            hs[3] = fmaf(am0[3], s0, fmaf(am1[3], s1, v[3])); o4.w = hs[3];
            *(float4*)(base + (size_t)tt * H_DIM) = o4;
        }
    }
}

// ---------------------------------------------------------------------------
extern "C" void kernel_launch(void* const* d_in, const int* in_sizes, int n_in,
                              void* d_out, int out_size) {
    const float* x = (const float*)d_in[0];   // [32, 2048, 128]
    const float* m = (const float*)d_in[1];   // [512, 2]
    const float* n = (const float*)d_in[2];   // [512, 2]
    const float* I = (const float*)d_in[3];   // [512, 128]
    float* out = (float*)d_out;               // [32, 2048, 512]

    (void)in_sizes; (void)n_in; (void)out_size;

    flags_zero<<<1, B_DIM * 16>>>();
    fused<<<B_DIM + (B_DIM * T_STEPS / 128) * (H_DIM / 128), 256>>>(x, m, n, I, out);
}